// round 7
// baseline (speedup 1.0000x reference)
#include <cuda_runtime.h>
#include <cuda_fp16.h>
#include <cstdint>

#define B_TOK   8192
#define NE      8
#define DIM     1024
#define TM      128
#define TN      256
#define KC      64
#define NCHUNK  (DIM / KC)
#define A_SUB   16384                  // 128 rows * 128B (one A split)
#define B_OFF   32768                  // B region offset within stage
#define STG     65536                  // Ahi(16K) | Alo(16K) | B(32K)
#define SMEM_DYN (3 * STG)             // 196608, 3-stage

// swizzled byte offset: 128B rows, 16B chunks
#define SWZ(row, c16) (((row) << 7) + ((((c16) ^ ((row) & 7))) << 4))

// ---------------- static device scratch ------------------------------------
__device__ int   g_count[NE];
__device__ int   g_off[NE];
__device__ int   g_tok [NE * B_TOK];
__device__ float g_gate[NE * B_TOK];
#define PAD_ROWS (2 * B_TOK + NE * 128)
__device__ __half g_Xhi[(size_t)B_TOK * DIM];
__device__ __half g_Xlo[(size_t)B_TOK * DIM];
__device__ __half g_Hhi[(size_t)PAD_ROWS * DIM];
__device__ __half g_Hlo[(size_t)PAD_ROWS * DIM];
__device__ __half g_wt[(size_t)2 * NE * DIM * DIM];   // [mtx][e][n][k] fp16

// ---------------- asm helpers -----------------------------------------------
__device__ __forceinline__ uint32_t smem_u32(const void* p) {
    uint32_t a;
    asm("{ .reg .u64 t; cvta.to.shared.u64 t, %1; cvt.u32.u64 %0, t; }" : "=r"(a) : "l"(p));
    return a;
}
#define LDSM4(r, a) \
    asm volatile("ldmatrix.sync.aligned.m8n8.x4.shared.b16 {%0,%1,%2,%3}, [%4];" \
        : "=r"((r)[0]), "=r"((r)[1]), "=r"((r)[2]), "=r"((r)[3]) : "r"(a))
#define MMA16816(c, a, b0v, b1v) \
    asm volatile("mma.sync.aligned.m16n8k16.row.col.f32.f16.f16.f32 " \
        "{%0,%1,%2,%3},{%4,%5,%6,%7},{%8,%9},{%0,%1,%2,%3};" \
        : "+f"((c)[0]), "+f"((c)[1]), "+f"((c)[2]), "+f"((c)[3]) \
        : "r"((a)[0]), "r"((a)[1]), "r"((a)[2]), "r"((a)[3]), "r"(b0v), "r"(b1v))
#define CP16(dst, src, sz) \
    asm volatile("cp.async.cg.shared.global [%0], [%1], 16, %2;" \
        :: "r"(dst), "l"(src), "r"(sz))
#define CP_COMMIT() asm volatile("cp.async.commit_group;" ::: "memory")
#define CP_WAIT1()  asm volatile("cp.async.wait_group 1;" ::: "memory")

// ---------------- small kernels ---------------------------------------------
__global__ void zero_counts_kernel() { if (threadIdx.x < NE) g_count[threadIdx.x] = 0; }

__global__ void offsets_kernel() {
    if (threadIdx.x == 0) {
        int s = 0;
        #pragma unroll
        for (int e = 0; e < NE; e++) { g_off[e] = s; s += (g_count[e] + 127) & ~127; }
    }
}

// fused: router (logits/top2/gating/buckets) + x -> fp16 hi/lo split
__global__ __launch_bounds__(256)
void router_split_kernel(const float* __restrict__ x,
                         const float* __restrict__ rw,
                         const float* __restrict__ rb,
                         float* __restrict__ gating_out) {
    const int warp = threadIdx.x >> 5, lane = threadIdx.x & 31;
    const int t = blockIdx.x * 8 + warp;
    const float* xr = x + (size_t)t * DIM;
    float acc[NE];
    #pragma unroll
    for (int e = 0; e < NE; e++) acc[e] = 0.f;

    #pragma unroll
    for (int u = 0; u < 8; u++) {
        const int i = u * 128 + lane * 4;            // float4 granularity
        const float4 v = *reinterpret_cast<const float4*>(xr + i);
        const float* f = reinterpret_cast<const float*>(&v);
        __half h[4], l[4];
        #pragma unroll
        for (int j = 0; j < 4; j++) {
            h[j] = __float2half(f[j]);
            l[j] = __float2half(f[j] - __half2float(h[j]));
            const float4* r4 = reinterpret_cast<const float4*>(rw + (size_t)(i + j) * NE);
            float4 a = r4[0], b = r4[1];
            acc[0] += f[j] * a.x; acc[1] += f[j] * a.y; acc[2] += f[j] * a.z; acc[3] += f[j] * a.w;
            acc[4] += f[j] * b.x; acc[5] += f[j] * b.y; acc[6] += f[j] * b.z; acc[7] += f[j] * b.w;
        }
        const size_t o4 = ((size_t)t * DIM + i) / 4;
        reinterpret_cast<uint2*>(g_Xhi)[o4] = *reinterpret_cast<uint2*>(h);
        reinterpret_cast<uint2*>(g_Xlo)[o4] = *reinterpret_cast<uint2*>(l);
    }
    #pragma unroll
    for (int e = 0; e < NE; e++)
        #pragma unroll
        for (int off = 16; off; off >>= 1) acc[e] += __shfl_down_sync(0xffffffffu, acc[e], off);
    if (lane == 0) {
        float lg[NE];
        #pragma unroll
        for (int e = 0; e < NE; e++) lg[e] = acc[e] + rb[e];
        int e1 = 0;
        #pragma unroll
        for (int e = 1; e < NE; e++) if (lg[e] > lg[e1]) e1 = e;
        int e2 = -1;
        #pragma unroll
        for (int e = 0; e < NE; e++) { if (e == e1) continue; if (e2 < 0 || lg[e] > lg[e2]) e2 = e; }
        float ex = expf(lg[e2] - lg[e1]);
        float g1 = 1.f / (1.f + ex), g2 = ex / (1.f + ex);
        if (gating_out) {
            float grow[NE];
            #pragma unroll
            for (int e = 0; e < NE; e++) grow[e] = 0.f;
            grow[e1] = g1; grow[e2] = g2;
            float* gp = gating_out + (size_t)t * NE;
            #pragma unroll
            for (int e = 0; e < NE; e++) gp[e] = grow[e];
        }
        int p1 = atomicAdd(&g_count[e1], 1);
        g_tok[e1 * B_TOK + p1] = t; g_gate[e1 * B_TOK + p1] = g1;
        int p2 = atomicAdd(&g_count[e2], 1);
        g_tok[e2 * B_TOK + p2] = t; g_gate[e2 * B_TOK + p2] = g2;
    }
}

// transpose weights to fp16: w[mtx][e][k][n] -> wt[mtx][e][n][k]
__global__ __launch_bounds__(256, 4)
void wsplit_kernel(const float* __restrict__ w1, const float* __restrict__ w2) {
    __shared__ float t[32][33];
    const int z = blockIdx.z;
    const float* w = ((z >> 3) ? w2 : w1) + ((size_t)(z & 7) << 20);
    __half* dh = g_wt + ((size_t)z << 20);
    const int n0 = blockIdx.x * 32, k0 = blockIdx.y * 32;
    const int tx = threadIdx.x & 31, ty = threadIdx.x >> 5;
    #pragma unroll
    for (int i = 0; i < 4; i++)
        t[ty + 8 * i][tx] = w[(size_t)(k0 + ty + 8 * i) * DIM + n0 + tx];
    __syncthreads();
    #pragma unroll
    for (int i = 0; i < 4; i++)
        dh[(size_t)(n0 + ty + 8 * i) * DIM + k0 + tx] = __float2half(t[tx][ty + 8 * i]);
}

// ---------------- grouped GEMM: fp16 2-term, 512 thr, warp tile 32x64 --------
template <int STAGE>
__global__ __launch_bounds__(512)
void gemm_mma(const float* __restrict__ bias, float* __restrict__ fused) {
    const int e   = blockIdx.z;
    const int cnt = g_count[e];
    const int m0  = blockIdx.y * TM;
    if (m0 >= cnt) return;
    const int n0     = blockIdx.x * TN;
    const int padoff = g_off[e];

    extern __shared__ char smem[];
    const uint32_t sbase = smem_u32(smem);
    const int tid  = threadIdx.x;
    const int lane = tid & 31, warp = tid >> 5;
    const int wm = (warp & 3) * 32, wn = (warp >> 2) * 64;

    // ---- cp.async assignments ----
    // A: 1024 slots (128 rows x 8 c16), 2 per thread (hi+lo each)
    // B: 2048 slots (256 rows x 8 c16), 4 per thread
    const __half* aSrc[2];
    uint32_t aDst[2], aSz[2];
    const ptrdiff_t dA = (STAGE == 1)
        ? (const char*)g_Xlo - (const char*)g_Xhi
        : (const char*)g_Hlo - (const char*)g_Hhi;
    #pragma unroll
    for (int j = 0; j < 2; j++) {
        const int id = tid + 512 * j;
        const int row = id >> 3, c16 = id & 7;
        const bool valid = (m0 + row) < cnt;
        size_t rbase;
        if (STAGE == 1)
            rbase = (size_t)(valid ? g_tok[e * B_TOK + m0 + row] : 0) * DIM;
        else
            rbase = (size_t)(padoff + m0 + (valid ? row : 0)) * DIM;
        aSrc[j] = (STAGE == 1 ? g_Xhi : g_Hhi) + rbase + c16 * 8;
        aDst[j] = SWZ(row, c16);
        aSz[j]  = valid ? 16u : 0u;
    }
    const size_t wb = ((size_t)((STAGE - 1) * NE + e) << 20) + (size_t)n0 * DIM;
    const __half* bSrc0 = g_wt + wb + (size_t)(tid >> 3) * DIM + (tid & 7) * 8;
    const uint32_t bDst0 = B_OFF + SWZ(tid >> 3, tid & 7);

    auto issue = [&](int c, int sb3) {
        const int kb = c * KC;
        const uint32_t st = sbase + sb3 * STG;
        #pragma unroll
        for (int j = 0; j < 2; j++) {
            const char* s = (const char*)(aSrc[j] + kb);
            CP16(st + aDst[j],         s,      aSz[j]);
            CP16(st + aDst[j] + A_SUB, s + dA, aSz[j]);
        }
        #pragma unroll
        for (int j = 0; j < 4; j++) {
            // B slot j: row advances by 64 per j  (512 threads / 8 c16)
            CP16(st + bDst0 + (j << 13),
                 (const char*)(bSrc0 + kb + (size_t)(j * 64) * DIM), 16u);
        }
    };

    float acc[2][8][4];
    #pragma unroll
    for (int i = 0; i < 2; i++)
        #pragma unroll
        for (int j = 0; j < 8; j++)
            #pragma unroll
            for (int k = 0; k < 4; k++) acc[i][j][k] = 0.f;

    issue(0, 0); CP_COMMIT();
    issue(1, 1); CP_COMMIT();

    const int lrow = lane & 15, lhalf = lane >> 4;
    int sb3 = 0;
    for (int c = 0; c < NCHUNK; c++) {
        CP_WAIT1();
        __syncthreads();
        {
            int nx = sb3 + 2; if (nx >= 3) nx -= 3;
            if (c + 2 < NCHUNK) issue(c + 2, nx);
            CP_COMMIT();
        }
        const uint32_t sb = sbase + sb3 * STG;
        #pragma unroll
        for (int ks = 0; ks < 4; ks++) {
            const int c16 = ks * 2 + lhalf;
            uint32_t ah[2][4], al[2][4];
            #pragma unroll
            for (int mt = 0; mt < 2; mt++) {
                const int row = wm + mt * 16 + lrow;
                const uint32_t aa = sb + SWZ(row, c16);
                LDSM4(ah[mt], aa);
                LDSM4(al[mt], aa + A_SUB);
            }
            uint32_t bh[4][4];
            #pragma unroll
            for (int p = 0; p < 4; p++) {
                const int row = wn + p * 16 + lrow;
                LDSM4(bh[p], sb + B_OFF + SWZ(row, c16));
            }
            #pragma unroll
            for (int mt = 0; mt < 2; mt++)
                #pragma unroll
                for (int nt = 0; nt < 8; nt++) {
                    const int p = nt >> 1, o = nt & 1;
                    MMA16816(acc[mt][nt], ah[mt], bh[p][o], bh[p][o + 2]);
                    MMA16816(acc[mt][nt], al[mt], bh[p][o], bh[p][o + 2]);
                }
        }
        sb3++; if (sb3 == 3) sb3 = 0;
    }

    // ---- epilogue ----
    const float* bp = bias + (size_t)e * DIM + n0 + wn + (lane & 3) * 2;
    #pragma unroll
    for (int mt = 0; mt < 2; mt++) {
        #pragma unroll
        for (int h = 0; h < 2; h++) {
            const int m = m0 + wm + mt * 16 + (lane >> 2) + h * 8;
            if (m >= cnt) continue;
            if (STAGE == 1) {
                size_t rb = (size_t)(padoff + m) * DIM + n0 + wn + (lane & 3) * 2;
                #pragma unroll
                for (int nt = 0; nt < 8; nt++) {
                    const float2 bsv = *reinterpret_cast<const float2*>(bp + nt * 8);
                    float vx = fmaxf(acc[mt][nt][2 * h]     + bsv.x, 0.f);
                    float vy = fmaxf(acc[mt][nt][2 * h + 1] + bsv.y, 0.f);
                    __half2 hi2, lo2;
                    hi2.x = __float2half(vx);
                    hi2.y = __float2half(vy);
                    lo2.x = __float2half(vx - __half2float(hi2.x));
                    lo2.y = __float2half(vy - __half2float(hi2.y));
                    *reinterpret_cast<__half2*>(&g_Hhi[rb + nt * 8]) = hi2;
                    *reinterpret_cast<__half2*>(&g_Hlo[rb + nt * 8]) = lo2;
                }
            } else {
                const int tok = g_tok[e * B_TOK + m];
                const float g = g_gate[e * B_TOK + m];
                float* fr = fused + (size_t)tok * DIM + n0 + wn + (lane & 3) * 2;
                #pragma unroll
                for (int nt = 0; nt < 8; nt++) {
                    const float2 bsv = *reinterpret_cast<const float2*>(bp + nt * 8);
                    atomicAdd(&fr[nt * 8],     g * (acc[mt][nt][2 * h]     + bsv.x));
                    atomicAdd(&fr[nt * 8 + 1], g * (acc[mt][nt][2 * h + 1] + bsv.y));
                }
            }
        }
    }
}

// ---------------- launch ------------------------------------------------------
extern "C" void kernel_launch(void* const* d_in, const int* in_sizes, int n_in,
                              void* d_out, int out_size) {
    const float* x  = (const float*)d_in[0];
    const float* rw = (const float*)d_in[1];
    const float* rb = (const float*)d_in[2];
    const float* w1 = (const float*)d_in[3];
    const float* b1 = (const float*)d_in[4];
    const float* w2 = (const float*)d_in[5];
    const float* b2 = (const float*)d_in[6];

    float* fused = (float*)d_out;
    const size_t fused_elems = (size_t)B_TOK * DIM;
    float* gating_out = nullptr;
    if ((size_t)out_size >= fused_elems + (size_t)B_TOK * NE)
        gating_out = fused + fused_elems;

    cudaFuncSetAttribute(gemm_mma<1>, cudaFuncAttributeMaxDynamicSharedMemorySize, SMEM_DYN);
    cudaFuncSetAttribute(gemm_mma<2>, cudaFuncAttributeMaxDynamicSharedMemorySize, SMEM_DYN);

    cudaMemsetAsync(d_out, 0, fused_elems * sizeof(float), 0);

    zero_counts_kernel<<<1, 32>>>();
    wsplit_kernel<<<dim3(32, 32, 16), 256>>>(w1, w2);
    router_split_kernel<<<B_TOK / 8, 256>>>(x, rw, rb, gating_out);
    offsets_kernel<<<1, 32>>>();

    dim3 grid(DIM / TN, 64, NE);   // (4, 64, 8); blocks past cnt exit early
    gemm_mma<1><<<grid, 512, SMEM_DYN>>>(b1, fused);
    gemm_mma<2><<<grid, 512, SMEM_DYN>>>(b2, fused);
}

// round 9
// speedup vs baseline: 1.5067x; 1.5067x over previous
#include <cuda_runtime.h>
#include <cuda_fp16.h>
#include <cstdint>

#define B_TOK   8192
#define NE      8
#define DIM     1024
#define TM      128
#define TN      256
#define KC      64
#define NCHUNK  (DIM / KC)
#define A_SUB   16384                  // 128 rows * 128B
#define B_OFF   16384                  // B region offset within stage
#define STG     49152                  // A(16K) | B(32K)
#define SMEM_DYN (3 * STG)             // 147456, 3-stage

// swizzled byte offset: 128B rows, 16B chunks
#define SWZ(row, c16) (((row) << 7) + ((((c16) ^ ((row) & 7))) << 4))

// ---------------- static device scratch ------------------------------------
__device__ int   g_count[NE];
__device__ int   g_off[NE];
__device__ int   g_tok [NE * B_TOK];
__device__ float g_gate[NE * B_TOK];
#define PAD_ROWS (2 * B_TOK + NE * 128)
__device__ __half g_X[(size_t)B_TOK * DIM];
__device__ __half g_H[(size_t)PAD_ROWS * DIM];
__device__ __half g_wt[(size_t)2 * NE * DIM * DIM];   // [mtx][e][n][k] fp16

// ---------------- asm helpers -----------------------------------------------
__device__ __forceinline__ uint32_t smem_u32(const void* p) {
    uint32_t a;
    asm("{ .reg .u64 t; cvta.to.shared.u64 t, %1; cvt.u32.u64 %0, t; }" : "=r"(a) : "l"(p));
    return a;
}
#define LDSM4(r, a) \
    asm volatile("ldmatrix.sync.aligned.m8n8.x4.shared.b16 {%0,%1,%2,%3}, [%4];" \
        : "=r"((r)[0]), "=r"((r)[1]), "=r"((r)[2]), "=r"((r)[3]) : "r"(a))
#define MMA16816(c, a, b0v, b1v) \
    asm volatile("mma.sync.aligned.m16n8k16.row.col.f32.f16.f16.f32 " \
        "{%0,%1,%2,%3},{%4,%5,%6,%7},{%8,%9},{%0,%1,%2,%3};" \
        : "+f"((c)[0]), "+f"((c)[1]), "+f"((c)[2]), "+f"((c)[3]) \
        : "r"((a)[0]), "r"((a)[1]), "r"((a)[2]), "r"((a)[3]), "r"(b0v), "r"(b1v))
#define CP16(dst, src, sz) \
    asm volatile("cp.async.cg.shared.global [%0], [%1], 16, %2;" \
        :: "r"(dst), "l"(src), "r"(sz))
#define CP_COMMIT() asm volatile("cp.async.commit_group;" ::: "memory")
#define CP_WAIT1()  asm volatile("cp.async.wait_group 1;" ::: "memory")

// ---------------- small kernels ---------------------------------------------
__global__ void zero_counts_kernel() { if (threadIdx.x < NE) g_count[threadIdx.x] = 0; }

__global__ void offsets_kernel() {
    if (threadIdx.x == 0) {
        int s = 0;
        #pragma unroll
        for (int e = 0; e < NE; e++) { g_off[e] = s; s += (g_count[e] + 127) & ~127; }
    }
}

// fused: router (logits/top2/gating/buckets) + x -> fp16
__global__ __launch_bounds__(256)
void router_split_kernel(const float* __restrict__ x,
                         const float* __restrict__ rw,
                         const float* __restrict__ rb,
                         float* __restrict__ gating_out) {
    const int warp = threadIdx.x >> 5, lane = threadIdx.x & 31;
    const int t = blockIdx.x * 8 + warp;
    const float* xr = x + (size_t)t * DIM;
    float acc[NE];
    #pragma unroll
    for (int e = 0; e < NE; e++) acc[e] = 0.f;

    #pragma unroll
    for (int u = 0; u < 8; u++) {
        const int i = u * 128 + lane * 4;
        const float4 v = *reinterpret_cast<const float4*>(xr + i);
        const float* f = reinterpret_cast<const float*>(&v);
        __half h[4];
        #pragma unroll
        for (int j = 0; j < 4; j++) {
            h[j] = __float2half(f[j]);
            const float4* r4 = reinterpret_cast<const float4*>(rw + (size_t)(i + j) * NE);
            float4 a = r4[0], b = r4[1];
            acc[0] += f[j] * a.x; acc[1] += f[j] * a.y; acc[2] += f[j] * a.z; acc[3] += f[j] * a.w;
            acc[4] += f[j] * b.x; acc[5] += f[j] * b.y; acc[6] += f[j] * b.z; acc[7] += f[j] * b.w;
        }
        reinterpret_cast<uint2*>(g_X)[((size_t)t * DIM + i) / 4] = *reinterpret_cast<uint2*>(h);
    }
    #pragma unroll
    for (int e = 0; e < NE; e++)
        #pragma unroll
        for (int off = 16; off; off >>= 1) acc[e] += __shfl_down_sync(0xffffffffu, acc[e], off);
    if (lane == 0) {
        float lg[NE];
        #pragma unroll
        for (int e = 0; e < NE; e++) lg[e] = acc[e] + rb[e];
        int e1 = 0;
        #pragma unroll
        for (int e = 1; e < NE; e++) if (lg[e] > lg[e1]) e1 = e;
        int e2 = -1;
        #pragma unroll
        for (int e = 0; e < NE; e++) { if (e == e1) continue; if (e2 < 0 || lg[e] > lg[e2]) e2 = e; }
        float ex = expf(lg[e2] - lg[e1]);
        float g1 = 1.f / (1.f + ex), g2 = ex / (1.f + ex);
        if (gating_out) {
            float grow[NE];
            #pragma unroll
            for (int e = 0; e < NE; e++) grow[e] = 0.f;
            grow[e1] = g1; grow[e2] = g2;
            float* gp = gating_out + (size_t)t * NE;
            #pragma unroll
            for (int e = 0; e < NE; e++) gp[e] = grow[e];
        }
        int p1 = atomicAdd(&g_count[e1], 1);
        g_tok[e1 * B_TOK + p1] = t; g_gate[e1 * B_TOK + p1] = g1;
        int p2 = atomicAdd(&g_count[e2], 1);
        g_tok[e2 * B_TOK + p2] = t; g_gate[e2 * B_TOK + p2] = g2;
    }
}

// transpose weights to fp16: w[mtx][e][k][n] -> wt[mtx][e][n][k]
__global__ __launch_bounds__(256, 4)
void wsplit_kernel(const float* __restrict__ w1, const float* __restrict__ w2) {
    __shared__ float t[32][33];
    const int z = blockIdx.z;
    const float* w = ((z >> 3) ? w2 : w1) + ((size_t)(z & 7) << 20);
    __half* dh = g_wt + ((size_t)z << 20);
    const int n0 = blockIdx.x * 32, k0 = blockIdx.y * 32;
    const int tx = threadIdx.x & 31, ty = threadIdx.x >> 5;
    #pragma unroll
    for (int i = 0; i < 4; i++)
        t[ty + 8 * i][tx] = w[(size_t)(k0 + ty + 8 * i) * DIM + n0 + tx];
    __syncthreads();
    #pragma unroll
    for (int i = 0; i < 4; i++)
        dh[(size_t)(n0 + ty + 8 * i) * DIM + k0 + tx] = __float2half(t[tx][ty + 8 * i]);
}

// ---------------- grouped GEMM: single fp16, 512 thr, warp tile 32x64 --------
template <int STAGE>
__global__ __launch_bounds__(512)
void gemm_mma(const float* __restrict__ bias, float* __restrict__ fused) {
    const int e   = blockIdx.z;
    const int cnt = g_count[e];
    const int m0  = blockIdx.y * TM;
    if (m0 >= cnt) return;
    const int n0     = blockIdx.x * TN;
    const int padoff = g_off[e];

    extern __shared__ char smem[];
    const uint32_t sbase = smem_u32(smem);
    const int tid  = threadIdx.x;
    const int lane = tid & 31, warp = tid >> 5;
    const int wm = (warp & 3) * 32, wn = (warp >> 2) * 64;

    // ---- cp.async assignments ----
    const __half* aSrc[2];
    uint32_t aDst[2], aSz[2];
    #pragma unroll
    for (int j = 0; j < 2; j++) {
        const int id = tid + 512 * j;
        const int row = id >> 3, c16 = id & 7;
        const bool valid = (m0 + row) < cnt;
        size_t rbase;
        if (STAGE == 1)
            rbase = (size_t)(valid ? g_tok[e * B_TOK + m0 + row] : 0) * DIM;
        else
            rbase = (size_t)(padoff + m0 + (valid ? row : 0)) * DIM;
        aSrc[j] = (STAGE == 1 ? g_X : g_H) + rbase + c16 * 8;
        aDst[j] = SWZ(row, c16);
        aSz[j]  = valid ? 16u : 0u;
    }
    const size_t wb = ((size_t)((STAGE - 1) * NE + e) << 20) + (size_t)n0 * DIM;
    const __half* bSrc0 = g_wt + wb + (size_t)(tid >> 3) * DIM + (tid & 7) * 8;
    const uint32_t bDst0 = B_OFF + SWZ(tid >> 3, tid & 7);

    auto issue = [&](int c, int sb3) {
        const int kb = c * KC;
        const uint32_t st = sbase + sb3 * STG;
        #pragma unroll
        for (int j = 0; j < 2; j++)
            CP16(st + aDst[j], (const char*)(aSrc[j] + kb), aSz[j]);
        #pragma unroll
        for (int j = 0; j < 4; j++)
            CP16(st + bDst0 + (j << 13),
                 (const char*)(bSrc0 + kb + (size_t)(j * 64) * DIM), 16u);
    };

    float acc[2][8][4];
    #pragma unroll
    for (int i = 0; i < 2; i++)
        #pragma unroll
        for (int j = 0; j < 8; j++)
            #pragma unroll
            for (int k = 0; k < 4; k++) acc[i][j][k] = 0.f;

    issue(0, 0); CP_COMMIT();
    issue(1, 1); CP_COMMIT();

    const int lrow = lane & 15, lhalf = lane >> 4;
    int sb3 = 0;
    for (int c = 0; c < NCHUNK; c++) {
        CP_WAIT1();
        __syncthreads();
        {
            int nx = sb3 + 2; if (nx >= 3) nx -= 3;
            if (c + 2 < NCHUNK) issue(c + 2, nx);
            CP_COMMIT();
        }
        const uint32_t sb = sbase + sb3 * STG;
        #pragma unroll
        for (int ks = 0; ks < 4; ks++) {
            const int c16 = ks * 2 + lhalf;
            uint32_t ah[2][4];
            #pragma unroll
            for (int mt = 0; mt < 2; mt++)
                LDSM4(ah[mt], sb + SWZ(wm + mt * 16 + lrow, c16));
            uint32_t bh[4][4];
            #pragma unroll
            for (int p = 0; p < 4; p++)
                LDSM4(bh[p], sb + B_OFF + SWZ(wn + p * 16 + lrow, c16));
            #pragma unroll
            for (int mt = 0; mt < 2; mt++)
                #pragma unroll
                for (int nt = 0; nt < 8; nt++) {
                    const int p = nt >> 1, o = nt & 1;
                    MMA16816(acc[mt][nt], ah[mt], bh[p][o], bh[p][o + 2]);
                }
        }
        sb3++; if (sb3 == 3) sb3 = 0;
    }

    // ---- epilogue ----
    const float* bp = bias + (size_t)e * DIM + n0 + wn + (lane & 3) * 2;
    #pragma unroll
    for (int mt = 0; mt < 2; mt++) {
        #pragma unroll
        for (int h = 0; h < 2; h++) {
            const int m = m0 + wm + mt * 16 + (lane >> 2) + h * 8;
            if (m >= cnt) continue;
            if (STAGE == 1) {
                size_t rb = (size_t)(padoff + m) * DIM + n0 + wn + (lane & 3) * 2;
                #pragma unroll
                for (int nt = 0; nt < 8; nt++) {
                    const float2 bsv = *reinterpret_cast<const float2*>(bp + nt * 8);
                    __half2 hv;
                    hv.x = __float2half(fmaxf(acc[mt][nt][2 * h]     + bsv.x, 0.f));
                    hv.y = __float2half(fmaxf(acc[mt][nt][2 * h + 1] + bsv.y, 0.f));
                    *reinterpret_cast<__half2*>(&g_H[rb + nt * 8]) = hv;
                }
            } else {
                const int tok = g_tok[e * B_TOK + m];
                const float g = g_gate[e * B_TOK + m];
                float* fr = fused + (size_t)tok * DIM + n0 + wn + (lane & 3) * 2;
                #pragma unroll
                for (int nt = 0; nt < 8; nt++) {
                    const float2 bsv = *reinterpret_cast<const float2*>(bp + nt * 8);
                    atomicAdd(&fr[nt * 8],     g * (acc[mt][nt][2 * h]     + bsv.x));
                    atomicAdd(&fr[nt * 8 + 1], g * (acc[mt][nt][2 * h + 1] + bsv.y));
                }
            }
        }
    }
}

// ---------------- launch ------------------------------------------------------
extern "C" void kernel_launch(void* const* d_in, const int* in_sizes, int n_in,
                              void* d_out, int out_size) {
    const float* x  = (const float*)d_in[0];
    const float* rw = (const float*)d_in[1];
    const float* rb = (const float*)d_in[2];
    const float* w1 = (const float*)d_in[3];
    const float* b1 = (const float*)d_in[4];
    const float* w2 = (const float*)d_in[5];
    const float* b2 = (const float*)d_in[6];

    float* fused = (float*)d_out;
    const size_t fused_elems = (size_t)B_TOK * DIM;
    float* gating_out = nullptr;
    if ((size_t)out_size >= fused_elems + (size_t)B_TOK * NE)
        gating_out = fused + fused_elems;

    cudaFuncSetAttribute(gemm_mma<1>, cudaFuncAttributeMaxDynamicSharedMemorySize, SMEM_DYN);
    cudaFuncSetAttribute(gemm_mma<2>, cudaFuncAttributeMaxDynamicSharedMemorySize, SMEM_DYN);

    cudaMemsetAsync(d_out, 0, fused_elems * sizeof(float), 0);

    zero_counts_kernel<<<1, 32>>>();
    wsplit_kernel<<<dim3(32, 32, 16), 256>>>(w1, w2);
    router_split_kernel<<<B_TOK / 8, 256>>>(x, rw, rb, gating_out);
    offsets_kernel<<<1, 32>>>();

    dim3 grid(DIM / TN, 64, NE);   // (4, 64, 8); blocks past cnt exit early
    gemm_mma<1><<<grid, 512, SMEM_DYN>>>(b1, fused);
    gemm_mma<2><<<grid, 512, SMEM_DYN>>>(b2, fused);
}

// round 12
// speedup vs baseline: 1.5508x; 1.0292x over previous
#include <cuda_runtime.h>
#include <cuda_fp16.h>
#include <cstdint>

#define B_TOK   8192
#define NE      8
#define DIM     1024
#define TM      128
#define TN      256
#define KC      64
#define NCHUNK  (DIM / KC)
#define A_SUB   16384
#define B_OFF   16384
#define STG     49152                  // A(16K) | B(32K)
#define SMEM_DYN (3 * STG)             // 147456, 3-stage

#define SWZ(row, c16) (((row) << 7) + ((((c16) ^ ((row) & 7))) << 4))

#define ROUTER_BLOCKS 1024
#define WSPLIT_BLOCKS 16384

// ---------------- static device scratch ------------------------------------
__device__ int   g_ctrl[NE + 1];       // [0..7] counts, [8] done-counter (memset to 0)
__device__ int   g_off[NE];
__device__ int   g_tok [NE * B_TOK];
__device__ float g_gate[NE * B_TOK];
#define PAD_ROWS (2 * B_TOK + NE * 128)
__device__ __half g_X[(size_t)B_TOK * DIM];
__device__ __half g_H[(size_t)PAD_ROWS * DIM];
__device__ __half g_wt[(size_t)2 * NE * DIM * DIM];   // [mtx][e][n][k] fp16

// ---------------- asm helpers -----------------------------------------------
__device__ __forceinline__ uint32_t smem_u32(const void* p) {
    uint32_t a;
    asm("{ .reg .u64 t; cvta.to.shared.u64 t, %1; cvt.u32.u64 %0, t; }" : "=r"(a) : "l"(p));
    return a;
}
#define LDSM4(r, a) \
    asm volatile("ldmatrix.sync.aligned.m8n8.x4.shared.b16 {%0,%1,%2,%3}, [%4];" \
        : "=r"((r)[0]), "=r"((r)[1]), "=r"((r)[2]), "=r"((r)[3]) : "r"(a))
#define MMA16816(c, a, b0v, b1v) \
    asm volatile("mma.sync.aligned.m16n8k16.row.col.f32.f16.f16.f32 " \
        "{%0,%1,%2,%3},{%4,%5,%6,%7},{%8,%9},{%0,%1,%2,%3};" \
        : "+f"((c)[0]), "+f"((c)[1]), "+f"((c)[2]), "+f"((c)[3]) \
        : "r"((a)[0]), "r"((a)[1]), "r"((a)[2]), "r"((a)[3]), "r"(b0v), "r"(b1v))
#define CP16(dst, src, sz) \
    asm volatile("cp.async.cg.shared.global [%0], [%1], 16, %2;" \
        :: "r"(dst), "l"(src), "r"(sz))
#define CP_COMMIT() asm volatile("cp.async.commit_group;" ::: "memory")
#define CP_WAIT1()  asm volatile("cp.async.wait_group 1;" ::: "memory")

// ---------------- fused prep: router+xsplit (blocks 0..1023) || wsplit -------
__global__ __launch_bounds__(256)
void prep_kernel(const float* __restrict__ x,
                 const float* __restrict__ rw,
                 const float* __restrict__ rb,
                 const float* __restrict__ w1,
                 const float* __restrict__ w2,
                 float* __restrict__ gating_out) {
    if (blockIdx.x < ROUTER_BLOCKS) {
        // ---------------- router + x->fp16 ----------------
        const int warp = threadIdx.x >> 5, lane = threadIdx.x & 31;
        const int t = blockIdx.x * 8 + warp;
        const float* xr = x + (size_t)t * DIM;
        float acc[NE];
        #pragma unroll
        for (int e = 0; e < NE; e++) acc[e] = 0.f;

        #pragma unroll
        for (int u = 0; u < 8; u++) {
            const int i = u * 128 + lane * 4;
            const float4 v = *reinterpret_cast<const float4*>(xr + i);
            const float* f = reinterpret_cast<const float*>(&v);
            __half h[4];
            #pragma unroll
            for (int j = 0; j < 4; j++) {
                h[j] = __float2half(f[j]);
                const float4* r4 = reinterpret_cast<const float4*>(rw + (size_t)(i + j) * NE);
                float4 a = r4[0], b = r4[1];
                acc[0] += f[j] * a.x; acc[1] += f[j] * a.y; acc[2] += f[j] * a.z; acc[3] += f[j] * a.w;
                acc[4] += f[j] * b.x; acc[5] += f[j] * b.y; acc[6] += f[j] * b.z; acc[7] += f[j] * b.w;
            }
            reinterpret_cast<uint2*>(g_X)[((size_t)t * DIM + i) / 4] = *reinterpret_cast<uint2*>(h);
        }
        #pragma unroll
        for (int e = 0; e < NE; e++)
            #pragma unroll
            for (int off = 16; off; off >>= 1) acc[e] += __shfl_down_sync(0xffffffffu, acc[e], off);
        if (lane == 0) {
            float lg[NE];
            #pragma unroll
            for (int e = 0; e < NE; e++) lg[e] = acc[e] + rb[e];
            int e1 = 0;
            #pragma unroll
            for (int e = 1; e < NE; e++) if (lg[e] > lg[e1]) e1 = e;
            int e2 = -1;
            #pragma unroll
            for (int e = 0; e < NE; e++) { if (e == e1) continue; if (e2 < 0 || lg[e] > lg[e2]) e2 = e; }
            float ex = expf(lg[e2] - lg[e1]);
            float g1 = 1.f / (1.f + ex), g2 = ex / (1.f + ex);
            if (gating_out) {
                float grow[NE];
                #pragma unroll
                for (int e = 0; e < NE; e++) grow[e] = 0.f;
                grow[e1] = g1; grow[e2] = g2;
                float* gp = gating_out + (size_t)t * NE;
                #pragma unroll
                for (int e = 0; e < NE; e++) gp[e] = grow[e];
            }
            int p1 = atomicAdd(&g_ctrl[e1], 1);
            g_tok[e1 * B_TOK + p1] = t; g_gate[e1 * B_TOK + p1] = g1;
            int p2 = atomicAdd(&g_ctrl[e2], 1);
            g_tok[e2 * B_TOK + p2] = t; g_gate[e2 * B_TOK + p2] = g2;
        }
        // last router block computes padded offsets
        __syncthreads();
        if (threadIdx.x == 0) {
            __threadfence();
            if (atomicAdd(&g_ctrl[NE], 1) == ROUTER_BLOCKS - 1) {
                int s = 0;
                #pragma unroll
                for (int e = 0; e < NE; e++) { g_off[e] = s; s += (g_ctrl[e] + 127) & ~127; }
            }
        }
    } else {
        // ---------------- weight transpose + fp16 convert ----------------
        __shared__ float t[32][33];
        const int b = blockIdx.x - ROUTER_BLOCKS;     // 0..16383
        const int z = b >> 10;                        // matrix*8+expert
        const int rem = b & 1023;
        const float* w = ((z >> 3) ? w2 : w1) + ((size_t)(z & 7) << 20);
        __half* dh = g_wt + ((size_t)z << 20);
        const int n0 = (rem & 31) * 32, k0 = (rem >> 5) * 32;
        const int tx = threadIdx.x & 31, ty = threadIdx.x >> 5;
        #pragma unroll
        for (int i = 0; i < 4; i++)
            t[ty + 8 * i][tx] = w[(size_t)(k0 + ty + 8 * i) * DIM + n0 + tx];
        __syncthreads();
        #pragma unroll
        for (int i = 0; i < 4; i++)
            dh[(size_t)(n0 + ty + 8 * i) * DIM + k0 + tx] = __float2half(t[tx][ty + 8 * i]);
    }
}

// ---------------- grouped GEMM: single fp16, 512 thr, warp tile 32x64 --------
template <int STAGE>
__global__ __launch_bounds__(512)
void gemm_mma(const float* __restrict__ bias, float* __restrict__ fused) {
    const int e   = blockIdx.z;
    const int cnt = g_ctrl[e];
    const int m0  = blockIdx.y * TM;
    if (m0 >= cnt) return;
    const int n0     = blockIdx.x * TN;
    const int padoff = g_off[e];

    extern __shared__ char smem[];
    const uint32_t sbase = smem_u32(smem);
    const int tid  = threadIdx.x;
    const int lane = tid & 31, warp = tid >> 5;
    const int wm = (warp & 3) * 32, wn = (warp >> 2) * 64;

    const __half* aSrc[2];
    uint32_t aDst[2], aSz[2];
    #pragma unroll
    for (int j = 0; j < 2; j++) {
        const int id = tid + 512 * j;
        const int row = id >> 3, c16 = id & 7;
        const bool valid = (m0 + row) < cnt;
        size_t rbase;
        if (STAGE == 1)
            rbase = (size_t)(valid ? g_tok[e * B_TOK + m0 + row] : 0) * DIM;
        else
            rbase = (size_t)(padoff + m0 + (valid ? row : 0)) * DIM;
        aSrc[j] = (STAGE == 1 ? g_X : g_H) + rbase + c16 * 8;
        aDst[j] = SWZ(row, c16);
        aSz[j]  = valid ? 16u : 0u;
    }
    const size_t wb = ((size_t)((STAGE - 1) * NE + e) << 20) + (size_t)n0 * DIM;
    const __half* bSrc0 = g_wt + wb + (size_t)(tid >> 3) * DIM + (tid & 7) * 8;
    const uint32_t bDst0 = B_OFF + SWZ(tid >> 3, tid & 7);

    auto issue = [&](int c, int sb3) {
        const int kb = c * KC;
        const uint32_t st = sbase + sb3 * STG;
        #pragma unroll
        for (int j = 0; j < 2; j++)
            CP16(st + aDst[j], (const char*)(aSrc[j] + kb), aSz[j]);
        #pragma unroll
        for (int j = 0; j < 4; j++)
            CP16(st + bDst0 + (j << 13),
                 (const char*)(bSrc0 + kb + (size_t)(j * 64) * DIM), 16u);
    };

    float acc[2][8][4];
    #pragma unroll
    for (int i = 0; i < 2; i++)
        #pragma unroll
        for (int j = 0; j < 8; j++)
            #pragma unroll
            for (int k = 0; k < 4; k++) acc[i][j][k] = 0.f;

    issue(0, 0); CP_COMMIT();
    issue(1, 1); CP_COMMIT();

    const int lrow = lane & 15, lhalf = lane >> 4;
    int sb3 = 0;
    for (int c = 0; c < NCHUNK; c++) {
        CP_WAIT1();
        __syncthreads();
        {
            int nx = sb3 + 2; if (nx >= 3) nx -= 3;
            if (c + 2 < NCHUNK) issue(c + 2, nx);
            CP_COMMIT();
        }
        const uint32_t sb = sbase + sb3 * STG;
        #pragma unroll
        for (int ks = 0; ks < 4; ks++) {
            const int c16 = ks * 2 + lhalf;
            uint32_t ah[2][4];
            #pragma unroll
            for (int mt = 0; mt < 2; mt++)
                LDSM4(ah[mt], sb + SWZ(wm + mt * 16 + lrow, c16));
            uint32_t bh[4][4];
            #pragma unroll
            for (int p = 0; p < 4; p++)
                LDSM4(bh[p], sb + B_OFF + SWZ(wn + p * 16 + lrow, c16));
            #pragma unroll
            for (int mt = 0; mt < 2; mt++)
                #pragma unroll
                for (int nt = 0; nt < 8; nt++) {
                    const int p = nt >> 1, o = nt & 1;
                    MMA16816(acc[mt][nt], ah[mt], bh[p][o], bh[p][o + 2]);
                }
        }
        sb3++; if (sb3 == 3) sb3 = 0;
    }

    // ---- epilogue ----
    const float* bp = bias + (size_t)e * DIM + n0 + wn + (lane & 3) * 2;
    #pragma unroll
    for (int mt = 0; mt < 2; mt++) {
        #pragma unroll
        for (int h = 0; h < 2; h++) {
            const int m = m0 + wm + mt * 16 + (lane >> 2) + h * 8;
            if (m >= cnt) continue;
            if (STAGE == 1) {
                size_t rb = (size_t)(padoff + m) * DIM + n0 + wn + (lane & 3) * 2;
                #pragma unroll
                for (int nt = 0; nt < 8; nt++) {
                    const float2 bsv = *reinterpret_cast<const float2*>(bp + nt * 8);
                    __half2 hv;
                    hv.x = __float2half(fmaxf(acc[mt][nt][2 * h]     + bsv.x, 0.f));
                    hv.y = __float2half(fmaxf(acc[mt][nt][2 * h + 1] + bsv.y, 0.f));
                    *reinterpret_cast<__half2*>(&g_H[rb + nt * 8]) = hv;
                }
            } else {
                const int tok = g_tok[e * B_TOK + m];
                const float g = g_gate[e * B_TOK + m];
                float* fr = fused + (size_t)tok * DIM + n0 + wn + (lane & 3) * 2;
                #pragma unroll
                for (int nt = 0; nt < 8; nt++) {
                    const float2 bsv = *reinterpret_cast<const float2*>(bp + nt * 8);
                    atomicAdd(&fr[nt * 8],     g * (acc[mt][nt][2 * h]     + bsv.x));
                    atomicAdd(&fr[nt * 8 + 1], g * (acc[mt][nt][2 * h + 1] + bsv.y));
                }
            }
        }
    }
}

// ---------------- launch ------------------------------------------------------
extern "C" void kernel_launch(void* const* d_in, const int* in_sizes, int n_in,
                              void* d_out, int out_size) {
    const float* x  = (const float*)d_in[0];
    const float* rw = (const float*)d_in[1];
    const float* rb = (const float*)d_in[2];
    const float* w1 = (const float*)d_in[3];
    const float* b1 = (const float*)d_in[4];
    const float* w2 = (const float*)d_in[5];
    const float* b2 = (const float*)d_in[6];

    float* fused = (float*)d_out;
    const size_t fused_elems = (size_t)B_TOK * DIM;
    float* gating_out = nullptr;
    if ((size_t)out_size >= fused_elems + (size_t)B_TOK * NE)
        gating_out = fused + fused_elems;

    cudaFuncSetAttribute(gemm_mma<1>, cudaFuncAttributeMaxDynamicSharedMemorySize, SMEM_DYN);
    cudaFuncSetAttribute(gemm_mma<2>, cudaFuncAttributeMaxDynamicSharedMemorySize, SMEM_DYN);

    // zero counts+done-counter and the fused accumulator (both capture-safe)
    void* ctrl_ptr = nullptr;
    cudaGetSymbolAddress(&ctrl_ptr, g_ctrl);
    cudaMemsetAsync(ctrl_ptr, 0, (NE + 1) * sizeof(int), 0);
    cudaMemsetAsync(d_out, 0, fused_elems * sizeof(float), 0);

    prep_kernel<<<ROUTER_BLOCKS + WSPLIT_BLOCKS, 256>>>(x, rw, rb, w1, w2, gating_out);

    dim3 grid(DIM / TN, 64, NE);   // (4, 64, 8)
    gemm_mma<1><<<grid, 512, SMEM_DYN>>>(b1, fused);
    gemm_mma<2><<<grid, 512, SMEM_DYN>>>(b2, fused);
}

// round 13
// speedup vs baseline: 1.7131x; 1.1047x over previous
#include <cuda_runtime.h>
#include <cuda_fp16.h>
#include <cstdint>

#define B_TOK   8192
#define NE      8
#define DIM     1024
#define TM      128
#define TN      256
#define KC      64
#define NCHUNK  (DIM / KC)
#define A_SUB   16384
#define B_OFF   16384
#define STG     49152                  // A(16K,[m][k]) | B(32K,[k][n])
#define SMEM_DYN (3 * STG)             // 147456, 3-stage

// A region: 128 rows x 128B ; B region: 64 rows x 512B
#define SWZ(row, c16)  (((row) << 7) + ((((c16) ^ ((row) & 7))) << 4))
#define SWZB(row, c16) (((row) << 9) + ((((c16) ^ ((row) & 7))) << 4))

#define ROUTER_BLOCKS 1024
#define CVT_BLOCKS    16384
#define F4_PER_MTX    (NE * DIM * DIM / 4)

// ---------------- static device scratch ------------------------------------
__device__ int   g_ctrl[NE + 1];       // [0..7] counts, [8] done-counter
__device__ int   g_off[NE];
__device__ int   g_tok [NE * B_TOK];
__device__ float g_gate[NE * B_TOK];
#define PAD_ROWS (2 * B_TOK + NE * 128)
__device__ __half g_X[(size_t)B_TOK * DIM];
__device__ __half g_H[(size_t)PAD_ROWS * DIM];
__device__ __half g_w16[(size_t)2 * NE * DIM * DIM];  // [mtx][e][k][n] fp16 (NOT transposed)

// ---------------- asm helpers -----------------------------------------------
__device__ __forceinline__ uint32_t smem_u32(const void* p) {
    uint32_t a;
    asm("{ .reg .u64 t; cvta.to.shared.u64 t, %1; cvt.u32.u64 %0, t; }" : "=r"(a) : "l"(p));
    return a;
}
#define LDSM4(r, a) \
    asm volatile("ldmatrix.sync.aligned.m8n8.x4.shared.b16 {%0,%1,%2,%3}, [%4];" \
        : "=r"((r)[0]), "=r"((r)[1]), "=r"((r)[2]), "=r"((r)[3]) : "r"(a))
#define LDSM4T(r, a) \
    asm volatile("ldmatrix.sync.aligned.m8n8.x4.trans.shared.b16 {%0,%1,%2,%3}, [%4];" \
        : "=r"((r)[0]), "=r"((r)[1]), "=r"((r)[2]), "=r"((r)[3]) : "r"(a))
#define MMA16816(c, a, b0v, b1v) \
    asm volatile("mma.sync.aligned.m16n8k16.row.col.f32.f16.f16.f32 " \
        "{%0,%1,%2,%3},{%4,%5,%6,%7},{%8,%9},{%0,%1,%2,%3};" \
        : "+f"((c)[0]), "+f"((c)[1]), "+f"((c)[2]), "+f"((c)[3]) \
        : "r"((a)[0]), "r"((a)[1]), "r"((a)[2]), "r"((a)[3]), "r"(b0v), "r"(b1v))
#define CP16(dst, src, sz) \
    asm volatile("cp.async.cg.shared.global [%0], [%1], 16, %2;" \
        :: "r"(dst), "l"(src), "r"(sz))
#define CP_COMMIT() asm volatile("cp.async.commit_group;" ::: "memory")
#define CP_WAIT1()  asm volatile("cp.async.wait_group 1;" ::: "memory")

// ---------------- fused prep: router+xsplit || streaming weight convert ------
__global__ __launch_bounds__(256)
void prep_kernel(const float* __restrict__ x,
                 const float* __restrict__ rw,
                 const float* __restrict__ rb,
                 const float* __restrict__ w1,
                 const float* __restrict__ w2,
                 float* __restrict__ gating_out) {
    if (blockIdx.x >= ROUTER_BLOCKS) {
        // ---- streaming fp32 -> fp16 convert of both weight tensors ----
        const size_t i4 = (size_t)(blockIdx.x - ROUTER_BLOCKS) * 256 + threadIdx.x;
        const float4 v = (i4 < F4_PER_MTX)
            ? reinterpret_cast<const float4*>(w1)[i4]
            : reinterpret_cast<const float4*>(w2)[i4 - F4_PER_MTX];
        __half h[4];
        h[0] = __float2half(v.x); h[1] = __float2half(v.y);
        h[2] = __float2half(v.z); h[3] = __float2half(v.w);
        reinterpret_cast<uint2*>(g_w16)[i4] = *reinterpret_cast<uint2*>(h);
        return;
    }
    // ---------------- router + x->fp16 ----------------
    const int warp = threadIdx.x >> 5, lane = threadIdx.x & 31;
    const int t = blockIdx.x * 8 + warp;
    const float* xr = x + (size_t)t * DIM;
    float acc[NE];
    #pragma unroll
    for (int e = 0; e < NE; e++) acc[e] = 0.f;

    #pragma unroll
    for (int u = 0; u < 8; u++) {
        const int i = u * 128 + lane * 4;
        const float4 v = *reinterpret_cast<const float4*>(xr + i);
        const float* f = reinterpret_cast<const float*>(&v);
        __half h[4];
        #pragma unroll
        for (int j = 0; j < 4; j++) {
            h[j] = __float2half(f[j]);
            const float4* r4 = reinterpret_cast<const float4*>(rw + (size_t)(i + j) * NE);
            float4 a = r4[0], b = r4[1];
            acc[0] += f[j] * a.x; acc[1] += f[j] * a.y; acc[2] += f[j] * a.z; acc[3] += f[j] * a.w;
            acc[4] += f[j] * b.x; acc[5] += f[j] * b.y; acc[6] += f[j] * b.z; acc[7] += f[j] * b.w;
        }
        reinterpret_cast<uint2*>(g_X)[((size_t)t * DIM + i) / 4] = *reinterpret_cast<uint2*>(h);
    }
    #pragma unroll
    for (int e = 0; e < NE; e++)
        #pragma unroll
        for (int off = 16; off; off >>= 1) acc[e] += __shfl_down_sync(0xffffffffu, acc[e], off);
    if (lane == 0) {
        float lg[NE];
        #pragma unroll
        for (int e = 0; e < NE; e++) lg[e] = acc[e] + rb[e];
        int e1 = 0;
        #pragma unroll
        for (int e = 1; e < NE; e++) if (lg[e] > lg[e1]) e1 = e;
        int e2 = -1;
        #pragma unroll
        for (int e = 0; e < NE; e++) { if (e == e1) continue; if (e2 < 0 || lg[e] > lg[e2]) e2 = e; }
        float ex = expf(lg[e2] - lg[e1]);
        float g1 = 1.f / (1.f + ex), g2 = ex / (1.f + ex);
        if (gating_out) {
            float grow[NE];
            #pragma unroll
            for (int e = 0; e < NE; e++) grow[e] = 0.f;
            grow[e1] = g1; grow[e2] = g2;
            float* gp = gating_out + (size_t)t * NE;
            #pragma unroll
            for (int e = 0; e < NE; e++) gp[e] = grow[e];
        }
        int p1 = atomicAdd(&g_ctrl[e1], 1);
        g_tok[e1 * B_TOK + p1] = t; g_gate[e1 * B_TOK + p1] = g1;
        int p2 = atomicAdd(&g_ctrl[e2], 1);
        g_tok[e2 * B_TOK + p2] = t; g_gate[e2 * B_TOK + p2] = g2;
    }
    __syncthreads();
    if (threadIdx.x == 0) {
        __threadfence();
        if (atomicAdd(&g_ctrl[NE], 1) == ROUTER_BLOCKS - 1) {
            int s = 0;
            #pragma unroll
            for (int e = 0; e < NE; e++) { g_off[e] = s; s += (g_ctrl[e] + 127) & ~127; }
        }
    }
}

// ---------------- grouped GEMM: fp16, B consumed MN-major via ldmatrix.trans -
template <int STAGE>
__global__ __launch_bounds__(512)
void gemm_mma(const float* __restrict__ bias, float* __restrict__ fused) {
    const int e   = blockIdx.z;
    const int cnt = g_ctrl[e];
    const int m0  = blockIdx.y * TM;
    if (m0 >= cnt) return;
    const int n0     = blockIdx.x * TN;
    const int padoff = g_off[e];

    extern __shared__ char smem[];
    const uint32_t sbase = smem_u32(smem);
    const int tid  = threadIdx.x;
    const int lane = tid & 31, warp = tid >> 5;
    const int wm = (warp & 3) * 32, wn = (warp >> 2) * 64;

    // ---- A cp.async: 1024 slots (128 rows x 8 c16), 2 per thread ----
    const __half* aSrc[2];
    uint32_t aDst[2], aSz[2];
    #pragma unroll
    for (int j = 0; j < 2; j++) {
        const int id = tid + 512 * j;
        const int row = id >> 3, c16 = id & 7;
        const bool valid = (m0 + row) < cnt;
        size_t rbase;
        if (STAGE == 1)
            rbase = (size_t)(valid ? g_tok[e * B_TOK + m0 + row] : 0) * DIM;
        else
            rbase = (size_t)(padoff + m0 + (valid ? row : 0)) * DIM;
        aSrc[j] = (STAGE == 1 ? g_X : g_H) + rbase + c16 * 8;
        aDst[j] = SWZ(row, c16);
        aSz[j]  = valid ? 16u : 0u;
    }
    // ---- B cp.async: [k][n] rows; 2048 slots (64 rows x 32 c16), 4/thread ---
    // slot id: row = id>>5 (0..63 within chunk), c16 = id&31 (n offset /8)
    const size_t wbase = ((size_t)((STAGE - 1) * NE + e) << 20);
    const int brow = tid >> 3 >> 2;            // tid>>5? compute via slots below
    const __half* bSrc[4];
    uint32_t bDst[4];
    #pragma unroll
    for (int j = 0; j < 4; j++) {
        const int id = tid + 512 * j;
        const int row = id >> 5, c16 = id & 31;
        bSrc[j] = g_w16 + wbase + (size_t)row * DIM + n0 + c16 * 8;
        bDst[j] = B_OFF + SWZB(row, c16);
    }

    auto issue = [&](int c, int sb3) {
        const uint32_t st = sbase + sb3 * STG;
        const int kb = c * KC;
        #pragma unroll
        for (int j = 0; j < 2; j++)
            CP16(st + aDst[j], (const char*)(aSrc[j] + kb), aSz[j]);
        const size_t koff = (size_t)kb * DIM;
        #pragma unroll
        for (int j = 0; j < 4; j++)
            CP16(st + bDst[j], (const char*)(bSrc[j] + koff), 16u);
    };

    float acc[2][8][4];
    #pragma unroll
    for (int i = 0; i < 2; i++)
        #pragma unroll
        for (int j = 0; j < 8; j++)
            #pragma unroll
            for (int k = 0; k < 4; k++) acc[i][j][k] = 0.f;

    issue(0, 0); CP_COMMIT();
    issue(1, 1); CP_COMMIT();

    const int lrow = lane & 15, lhalf = lane >> 4;
    int sb3 = 0;
    for (int c = 0; c < NCHUNK; c++) {
        CP_WAIT1();
        __syncthreads();
        {
            int nx = sb3 + 2; if (nx >= 3) nx -= 3;
            if (c + 2 < NCHUNK) issue(c + 2, nx);
            CP_COMMIT();
        }
        const uint32_t sb = sbase + sb3 * STG;
        #pragma unroll
        for (int ks = 0; ks < 4; ks++) {
            // A: [m][k] layout, k16 = 2 c16 units
            const int c16a = ks * 2 + lhalf;
            uint32_t ah[2][4];
            #pragma unroll
            for (int mt = 0; mt < 2; mt++)
                LDSM4(ah[mt], sb + SWZ(wm + mt * 16 + lrow, c16a));
            // B: [k][n] layout via ldmatrix.trans:
            //  lanes 0-15 -> rows k0..k15 ; lane>>4 -> +8 n
            uint32_t bt[4][4];
            const int browk = ks * 16 + lrow;
            #pragma unroll
            for (int p = 0; p < 4; p++) {
                const int nch = (wn >> 3) + p * 2 + lhalf;
                LDSM4T(bt[p], sb + B_OFF + SWZB(browk, nch));
            }
            #pragma unroll
            for (int mt = 0; mt < 2; mt++)
                #pragma unroll
                for (int nt = 0; nt < 8; nt++) {
                    const int p = nt >> 1, o = nt & 1;
                    MMA16816(acc[mt][nt], ah[mt], bt[p][2 * o], bt[p][2 * o + 1]);
                }
        }
        sb3++; if (sb3 == 3) sb3 = 0;
    }

    // ---- epilogue ----
    const float* bp = bias + (size_t)e * DIM + n0 + wn + (lane & 3) * 2;
    #pragma unroll
    for (int mt = 0; mt < 2; mt++) {
        #pragma unroll
        for (int h = 0; h < 2; h++) {
            const int m = m0 + wm + mt * 16 + (lane >> 2) + h * 8;
            if (m >= cnt) continue;
            if (STAGE == 1) {
                size_t rb = (size_t)(padoff + m) * DIM + n0 + wn + (lane & 3) * 2;
                #pragma unroll
                for (int nt = 0; nt < 8; nt++) {
                    const float2 bsv = *reinterpret_cast<const float2*>(bp + nt * 8);
                    __half2 hv;
                    hv.x = __float2half(fmaxf(acc[mt][nt][2 * h]     + bsv.x, 0.f));
                    hv.y = __float2half(fmaxf(acc[mt][nt][2 * h + 1] + bsv.y, 0.f));
                    *reinterpret_cast<__half2*>(&g_H[rb + nt * 8]) = hv;
                }
            } else {
                const int tok = g_tok[e * B_TOK + m];
                const float g = g_gate[e * B_TOK + m];
                float* fr = fused + (size_t)tok * DIM + n0 + wn + (lane & 3) * 2;
                #pragma unroll
                for (int nt = 0; nt < 8; nt++) {
                    const float2 bsv = *reinterpret_cast<const float2*>(bp + nt * 8);
                    atomicAdd(&fr[nt * 8],     g * (acc[mt][nt][2 * h]     + bsv.x));
                    atomicAdd(&fr[nt * 8 + 1], g * (acc[mt][nt][2 * h + 1] + bsv.y));
                }
            }
        }
    }
}

// ---------------- launch ------------------------------------------------------
extern "C" void kernel_launch(void* const* d_in, const int* in_sizes, int n_in,
                              void* d_out, int out_size) {
    const float* x  = (const float*)d_in[0];
    const float* rw = (const float*)d_in[1];
    const float* rb = (const float*)d_in[2];
    const float* w1 = (const float*)d_in[3];
    const float* b1 = (const float*)d_in[4];
    const float* w2 = (const float*)d_in[5];
    const float* b2 = (const float*)d_in[6];

    float* fused = (float*)d_out;
    const size_t fused_elems = (size_t)B_TOK * DIM;
    float* gating_out = nullptr;
    if ((size_t)out_size >= fused_elems + (size_t)B_TOK * NE)
        gating_out = fused + fused_elems;

    cudaFuncSetAttribute(gemm_mma<1>, cudaFuncAttributeMaxDynamicSharedMemorySize, SMEM_DYN);
    cudaFuncSetAttribute(gemm_mma<2>, cudaFuncAttributeMaxDynamicSharedMemorySize, SMEM_DYN);

    void* ctrl_ptr = nullptr;
    cudaGetSymbolAddress(&ctrl_ptr, g_ctrl);
    cudaMemsetAsync(ctrl_ptr, 0, (NE + 1) * sizeof(int), 0);
    cudaMemsetAsync(d_out, 0, fused_elems * sizeof(float), 0);

    prep_kernel<<<ROUTER_BLOCKS + CVT_BLOCKS, 256>>>(x, rw, rb, w1, w2, gating_out);

    dim3 grid(DIM / TN, 64, NE);   // (4, 64, 8)
    gemm_mma<1><<<grid, 512, SMEM_DYN>>>(b1, fused);
    gemm_mma<2><<<grid, 512, SMEM_DYN>>>(b2, fused);
}

// round 14
// speedup vs baseline: 1.9938x; 1.1638x over previous
#include <cuda_runtime.h>
#include <cuda_fp16.h>
#include <cstdint>

#define B_TOK   8192
#define NE      8
#define DIM     1024
#define TM      128
#define TN      256
#define KC      64
#define NCHUNK  (DIM / KC)
#define A_SUB   16384
#define B_OFF   16384
#define STG     49152                  // A(16K,[m][k]) | B(32K,[k][n])
#define SMEM_DYN (3 * STG)             // 147456, 3-stage

// A region: 128 rows x 128B ; B region: 64 rows x 512B
#define SWZ(row, c16)  (((row) << 7) + ((((c16) ^ ((row) & 7))) << 4))
#define SWZB(row, c16) (((row) << 9) + ((((c16) ^ ((row) & 7))) << 4))

#define ROUTER_BLOCKS 1024
#define CVT_BLOCKS    4096
#define F4_TOTAL      (2 * NE * DIM * DIM / 4)   // 4194304

// ---------------- static device scratch ------------------------------------
__device__ int   g_ctrl[NE + 1];       // [0..7] counts, [8] done-counter
__device__ int   g_off[NE];
__device__ int   g_tok [NE * B_TOK];
__device__ float g_gate[NE * B_TOK];
#define PAD_ROWS (2 * B_TOK + NE * 128)
__device__ __half g_X[(size_t)B_TOK * DIM];
__device__ __half g_H[(size_t)PAD_ROWS * DIM];
__device__ __half g_w16[(size_t)2 * NE * DIM * DIM];  // [mtx][e][k][n] fp16

// ---------------- asm helpers -----------------------------------------------
__device__ __forceinline__ uint32_t smem_u32(const void* p) {
    uint32_t a;
    asm("{ .reg .u64 t; cvta.to.shared.u64 t, %1; cvt.u32.u64 %0, t; }" : "=r"(a) : "l"(p));
    return a;
}
#define LDSM4(r, a) \
    asm volatile("ldmatrix.sync.aligned.m8n8.x4.shared.b16 {%0,%1,%2,%3}, [%4];" \
        : "=r"((r)[0]), "=r"((r)[1]), "=r"((r)[2]), "=r"((r)[3]) : "r"(a))
#define LDSM4T(r, a) \
    asm volatile("ldmatrix.sync.aligned.m8n8.x4.trans.shared.b16 {%0,%1,%2,%3}, [%4];" \
        : "=r"((r)[0]), "=r"((r)[1]), "=r"((r)[2]), "=r"((r)[3]) : "r"(a))
#define MMA16816(c, a, b0v, b1v) \
    asm volatile("mma.sync.aligned.m16n8k16.row.col.f32.f16.f16.f32 " \
        "{%0,%1,%2,%3},{%4,%5,%6,%7},{%8,%9},{%0,%1,%2,%3};" \
        : "+f"((c)[0]), "+f"((c)[1]), "+f"((c)[2]), "+f"((c)[3]) \
        : "r"((a)[0]), "r"((a)[1]), "r"((a)[2]), "r"((a)[3]), "r"(b0v), "r"(b1v))
#define CP16(dst, src, sz) \
    asm volatile("cp.async.cg.shared.global [%0], [%1], 16, %2;" \
        :: "r"(dst), "l"(src), "r"(sz))
#define CP_COMMIT() asm volatile("cp.async.commit_group;" ::: "memory")
#define CP_WAIT1()  asm volatile("cp.async.wait_group 1;" ::: "memory")

// ---------------- fused prep: router+xsplit || streaming weight convert ------
__global__ __launch_bounds__(256)
void prep_kernel(const float* __restrict__ x,
                 const float* __restrict__ rw,
                 const float* __restrict__ rb,
                 const float* __restrict__ w1,
                 const float* __restrict__ w2,
                 float* __restrict__ gating_out) {
    if (blockIdx.x >= ROUTER_BLOCKS) {
        // ---- streaming fp32 -> fp16 convert, 4 independent LDG.128/thread ----
        const size_t base = (size_t)(blockIdx.x - ROUTER_BLOCKS) * 1024 + threadIdx.x;
        float4 v[4];
        #pragma unroll
        for (int k = 0; k < 4; k++) {
            const size_t i4 = base + 256 * k;
            v[k] = (i4 < (size_t)F4_TOTAL / 2)
                ? reinterpret_cast<const float4*>(w1)[i4]
                : reinterpret_cast<const float4*>(w2)[i4 - F4_TOTAL / 2];
        }
        #pragma unroll
        for (int k = 0; k < 4; k++) {
            __half h[4];
            h[0] = __float2half(v[k].x); h[1] = __float2half(v[k].y);
            h[2] = __float2half(v[k].z); h[3] = __float2half(v[k].w);
            reinterpret_cast<uint2*>(g_w16)[base + 256 * k] = *reinterpret_cast<uint2*>(h);
        }
        return;
    }
    // ---------------- router + x->fp16 ----------------
    __shared__ float rwT[NE][DIM];     // 32KB, transposed router weights
    {
        // coalesced load of rw [1024][8] -> rwT[e][i]
        #pragma unroll
        for (int k = 0; k < 8; k++) {
            const int idx = threadIdx.x + 256 * k;        // float4 index, 2048 total
            const float4 f = reinterpret_cast<const float4*>(rw)[idx];
            const int row = idx >> 1, e0 = (idx & 1) * 4;
            rwT[e0 + 0][row] = f.x; rwT[e0 + 1][row] = f.y;
            rwT[e0 + 2][row] = f.z; rwT[e0 + 3][row] = f.w;
        }
    }
    __syncthreads();

    const int warp = threadIdx.x >> 5, lane = threadIdx.x & 31;
    const int t = blockIdx.x * 8 + warp;
    const float* xr = x + (size_t)t * DIM;
    float acc[NE];
    #pragma unroll
    for (int e = 0; e < NE; e++) acc[e] = 0.f;

    #pragma unroll
    for (int u = 0; u < 8; u++) {
        const int i = u * 128 + lane * 4;
        const float4 v = *reinterpret_cast<const float4*>(xr + i);
        const float* f = reinterpret_cast<const float*>(&v);
        __half h[4];
        #pragma unroll
        for (int j = 0; j < 4; j++) h[j] = __float2half(f[j]);
        reinterpret_cast<uint2*>(g_X)[((size_t)t * DIM + i) / 4] = *reinterpret_cast<uint2*>(h);
        #pragma unroll
        for (int e = 0; e < NE; e++) {
            const float4 r = *reinterpret_cast<const float4*>(&rwT[e][i]);
            acc[e] += f[0] * r.x + f[1] * r.y + f[2] * r.z + f[3] * r.w;
        }
    }
    #pragma unroll
    for (int e = 0; e < NE; e++)
        #pragma unroll
        for (int off = 16; off; off >>= 1) acc[e] += __shfl_down_sync(0xffffffffu, acc[e], off);
    if (lane == 0) {
        float lg[NE];
        #pragma unroll
        for (int e = 0; e < NE; e++) lg[e] = acc[e] + rb[e];
        int e1 = 0;
        #pragma unroll
        for (int e = 1; e < NE; e++) if (lg[e] > lg[e1]) e1 = e;
        int e2 = -1;
        #pragma unroll
        for (int e = 0; e < NE; e++) { if (e == e1) continue; if (e2 < 0 || lg[e] > lg[e2]) e2 = e; }
        float ex = expf(lg[e2] - lg[e1]);
        float g1 = 1.f / (1.f + ex), g2 = ex / (1.f + ex);
        if (gating_out) {
            float grow[NE];
            #pragma unroll
            for (int e = 0; e < NE; e++) grow[e] = 0.f;
            grow[e1] = g1; grow[e2] = g2;
            float* gp = gating_out + (size_t)t * NE;
            #pragma unroll
            for (int e = 0; e < NE; e++) gp[e] = grow[e];
        }
        int p1 = atomicAdd(&g_ctrl[e1], 1);
        g_tok[e1 * B_TOK + p1] = t; g_gate[e1 * B_TOK + p1] = g1;
        int p2 = atomicAdd(&g_ctrl[e2], 1);
        g_tok[e2 * B_TOK + p2] = t; g_gate[e2 * B_TOK + p2] = g2;
    }
    __syncthreads();
    if (threadIdx.x == 0) {
        __threadfence();
        if (atomicAdd(&g_ctrl[NE], 1) == ROUTER_BLOCKS - 1) {
            int s = 0;
            #pragma unroll
            for (int e = 0; e < NE; e++) { g_off[e] = s; s += (g_ctrl[e] + 127) & ~127; }
        }
    }
}

// ---------------- grouped GEMM: fp16, B consumed MN-major via ldmatrix.trans -
template <int STAGE>
__global__ __launch_bounds__(512)
void gemm_mma(const float* __restrict__ bias, float* __restrict__ fused) {
    const int e   = blockIdx.z;
    const int cnt = g_ctrl[e];
    const int m0  = blockIdx.y * TM;
    if (m0 >= cnt) return;
    const int n0     = blockIdx.x * TN;
    const int padoff = g_off[e];

    extern __shared__ char smem[];
    const uint32_t sbase = smem_u32(smem);
    const int tid  = threadIdx.x;
    const int lane = tid & 31, warp = tid >> 5;
    const int wm = (warp & 3) * 32, wn = (warp >> 2) * 64;

    const __half* aSrc[2];
    uint32_t aDst[2], aSz[2];
    #pragma unroll
    for (int j = 0; j < 2; j++) {
        const int id = tid + 512 * j;
        const int row = id >> 3, c16 = id & 7;
        const bool valid = (m0 + row) < cnt;
        size_t rbase;
        if (STAGE == 1)
            rbase = (size_t)(valid ? g_tok[e * B_TOK + m0 + row] : 0) * DIM;
        else
            rbase = (size_t)(padoff + m0 + (valid ? row : 0)) * DIM;
        aSrc[j] = (STAGE == 1 ? g_X : g_H) + rbase + c16 * 8;
        aDst[j] = SWZ(row, c16);
        aSz[j]  = valid ? 16u : 0u;
    }
    const size_t wbase = ((size_t)((STAGE - 1) * NE + e) << 20);
    const __half* bSrc[4];
    uint32_t bDst[4];
    #pragma unroll
    for (int j = 0; j < 4; j++) {
        const int id = tid + 512 * j;
        const int row = id >> 5, c16 = id & 31;
        bSrc[j] = g_w16 + wbase + (size_t)row * DIM + n0 + c16 * 8;
        bDst[j] = B_OFF + SWZB(row, c16);
    }

    auto issue = [&](int c, int sb3) {
        const uint32_t st = sbase + sb3 * STG;
        const int kb = c * KC;
        #pragma unroll
        for (int j = 0; j < 2; j++)
            CP16(st + aDst[j], (const char*)(aSrc[j] + kb), aSz[j]);
        const size_t koff = (size_t)kb * DIM;
        #pragma unroll
        for (int j = 0; j < 4; j++)
            CP16(st + bDst[j], (const char*)(bSrc[j] + koff), 16u);
    };

    float acc[2][8][4];
    #pragma unroll
    for (int i = 0; i < 2; i++)
        #pragma unroll
        for (int j = 0; j < 8; j++)
            #pragma unroll
            for (int k = 0; k < 4; k++) acc[i][j][k] = 0.f;

    issue(0, 0); CP_COMMIT();
    issue(1, 1); CP_COMMIT();

    const int lrow = lane & 15, lhalf = lane >> 4;
    int sb3 = 0;
    for (int c = 0; c < NCHUNK; c++) {
        CP_WAIT1();
        __syncthreads();
        {
            int nx = sb3 + 2; if (nx >= 3) nx -= 3;
            if (c + 2 < NCHUNK) issue(c + 2, nx);
            CP_COMMIT();
        }
        const uint32_t sb = sbase + sb3 * STG;
        #pragma unroll
        for (int ks = 0; ks < 4; ks++) {
            const int c16a = ks * 2 + lhalf;
            uint32_t ah[2][4];
            #pragma unroll
            for (int mt = 0; mt < 2; mt++)
                LDSM4(ah[mt], sb + SWZ(wm + mt * 16 + lrow, c16a));
            uint32_t bt[4][4];
            const int browk = ks * 16 + lrow;
            #pragma unroll
            for (int p = 0; p < 4; p++) {
                const int nch = (wn >> 3) + p * 2 + lhalf;
                LDSM4T(bt[p], sb + B_OFF + SWZB(browk, nch));
            }
            #pragma unroll
            for (int mt = 0; mt < 2; mt++)
                #pragma unroll
                for (int nt = 0; nt < 8; nt++) {
                    const int p = nt >> 1, o = nt & 1;
                    MMA16816(acc[mt][nt], ah[mt], bt[p][2 * o], bt[p][2 * o + 1]);
                }
        }
        sb3++; if (sb3 == 3) sb3 = 0;
    }

    // ---- epilogue ----
    const float* bp = bias + (size_t)e * DIM + n0 + wn + (lane & 3) * 2;
    #pragma unroll
    for (int mt = 0; mt < 2; mt++) {
        #pragma unroll
        for (int h = 0; h < 2; h++) {
            const int m = m0 + wm + mt * 16 + (lane >> 2) + h * 8;
            if (m >= cnt) continue;
            if (STAGE == 1) {
                size_t rb = (size_t)(padoff + m) * DIM + n0 + wn + (lane & 3) * 2;
                #pragma unroll
                for (int nt = 0; nt < 8; nt++) {
                    const float2 bsv = *reinterpret_cast<const float2*>(bp + nt * 8);
                    __half2 hv;
                    hv.x = __float2half(fmaxf(acc[mt][nt][2 * h]     + bsv.x, 0.f));
                    hv.y = __float2half(fmaxf(acc[mt][nt][2 * h + 1] + bsv.y, 0.f));
                    *reinterpret_cast<__half2*>(&g_H[rb + nt * 8]) = hv;
                }
            } else {
                const int tok = g_tok[e * B_TOK + m];
                const float g = g_gate[e * B_TOK + m];
                float* fr = fused + (size_t)tok * DIM + n0 + wn + (lane & 3) * 2;
                #pragma unroll
                for (int nt = 0; nt < 8; nt++) {
                    const float2 bsv = *reinterpret_cast<const float2*>(bp + nt * 8);
                    atomicAdd(&fr[nt * 8],     g * (acc[mt][nt][2 * h]     + bsv.x));
                    atomicAdd(&fr[nt * 8 + 1], g * (acc[mt][nt][2 * h + 1] + bsv.y));
                }
            }
        }
    }
}

// ---------------- launch ------------------------------------------------------
extern "C" void kernel_launch(void* const* d_in, const int* in_sizes, int n_in,
                              void* d_out, int out_size) {
    const float* x  = (const float*)d_in[0];
    const float* rw = (const float*)d_in[1];
    const float* rb = (const float*)d_in[2];
    const float* w1 = (const float*)d_in[3];
    const float* b1 = (const float*)d_in[4];
    const float* w2 = (const float*)d_in[5];
    const float* b2 = (const float*)d_in[6];

    float* fused = (float*)d_out;
    const size_t fused_elems = (size_t)B_TOK * DIM;
    float* gating_out = nullptr;
    if ((size_t)out_size >= fused_elems + (size_t)B_TOK * NE)
        gating_out = fused + fused_elems;

    cudaFuncSetAttribute(gemm_mma<1>, cudaFuncAttributeMaxDynamicSharedMemorySize, SMEM_DYN);
    cudaFuncSetAttribute(gemm_mma<2>, cudaFuncAttributeMaxDynamicSharedMemorySize, SMEM_DYN);

    void* ctrl_ptr = nullptr;
    cudaGetSymbolAddress(&ctrl_ptr, g_ctrl);
    cudaMemsetAsync(ctrl_ptr, 0, (NE + 1) * sizeof(int), 0);
    cudaMemsetAsync(d_out, 0, fused_elems * sizeof(float), 0);

    prep_kernel<<<ROUTER_BLOCKS + CVT_BLOCKS, 256>>>(x, rw, rb, w1, w2, gating_out);

    dim3 grid(DIM / TN, 64, NE);   // (4, 64, 8)
    gemm_mma<1><<<grid, 512, SMEM_DYN>>>(b1, fused);
    gemm_mma<2><<<grid, 512, SMEM_DYN>>>(b2, fused);
}